// round 7
// baseline (speedup 1.0000x reference)
#include <cuda_runtime.h>
#include <cstdint>

typedef unsigned long long u64;
typedef unsigned long long ull;

// ============================ problem constants ============================
#define N_   32
#define C_   256
#define H_   56
#define W_   56
#define PH_  58
#define PW_  58
#define PIX_ (H_*W_)                 // 3136
#define M_CNT_ (N_*PIX_)             // 100352
#define NW_  4                       // u64 words per pixel (256 ch)

// ============================ device scratch ============================
__device__ __align__(16) u64 g_Xp1[(size_t)N_*PH_*PW_*NW_];   // packed padded input (3.44 MB)
__device__ __align__(16) u64 g_Xp2[(size_t)N_*PH_*PW_*NW_];   // packed padded act2
__device__ __align__(16) u64 g_Wp1[9*C_*NW_];
__device__ __align__(16) u64 g_Wp2[9*C_*NW_];
__device__ int  g_c1[9*C_];
__device__ int  g_c2[9*C_];
__device__ __align__(16) short g_S1[(size_t)M_CNT_*C_];       // [pixel][cout] (51.4 MB)
__device__ __align__(16) short g_S2[(size_t)M_CNT_*C_];
__device__ ull g_sum1[C_], g_sq1[C_], g_sum2[C_], g_sq2[C_];
__device__ float g_a1[C_], g_b1[C_], g_a2[C_], g_b2[C_];

// ============================ setup kernels ============================
__global__ void zero_stats_k() {
    int i = threadIdx.x;
    g_sum1[i] = 0ull; g_sq1[i] = 0ull; g_sum2[i] = 0ull; g_sq2[i] = 0ull;
}

// pack weights: w [O=256][I=256][3][3] f32 -> Wp[t][cout][4] u64 (bit=1 means +1)
__global__ void pack_w_k(const float* __restrict__ w, u64* __restrict__ Wp) {
    int t = blockIdx.x;          // 0..8
    int c = threadIdx.x;         // cout
    int ky = t / 3, kx = t % 3;
    #pragma unroll
    for (int j = 0; j < NW_; ++j) {
        u64 bits = 0ull;
        #pragma unroll 4
        for (int cl = 0; cl < 64; ++cl) {
            int cin = j * 64 + cl;
            float v = w[(((size_t)c * C_ + cin) * 3 + ky) * 3 + kx];
            bits |= (u64)(v > 0.0f) << cl;
        }
        Wp[((size_t)t * C_ + c) * NW_ + j] = bits;
    }
}

// border corrections: corr[type][c] = sum over invalid taps of (256 - 2*popc(w_tap))
__global__ void corr_w_k(const u64* __restrict__ Wp, int* __restrict__ corr) {
    int c = threadIdx.x;
    int pc[9];
    #pragma unroll
    for (int t = 0; t < 9; ++t) {
        int s = 0;
        #pragma unroll
        for (int j = 0; j < NW_; ++j) s += __popcll(Wp[((size_t)t * C_ + c) * NW_ + j]);
        pc[t] = s;
    }
    for (int type = 0; type < 9; ++type) {
        int rt = type / 3, ct = type % 3;
        int s = 0;
        #pragma unroll
        for (int ky = 0; ky < 3; ++ky)
            #pragma unroll
            for (int kx = 0; kx < 3; ++kx) {
                bool rinv = (rt == 0 && ky == 0) || (rt == 2 && ky == 2);
                bool cinv = (ct == 0 && kx == 0) || (ct == 2 && kx == 2);
                if (rinv || cinv) s += 256 - 2 * pc[ky * 3 + kx];
            }
        corr[type * C_ + c] = s;
    }
}

// binarize x (NCHW f32) -> padded packed bitplanes, halo = 0 bits
__global__ void pack_x_k(const float* __restrict__ x, u64* __restrict__ Xp) {
    int px = threadIdx.x;   // 0..57
    int j  = threadIdx.y;   // 0..3
    int py = blockIdx.x;    // 0..57
    int n  = blockIdx.y;
    size_t oidx = (((size_t)n * PH_ + py) * PW_ + px) * NW_ + j;
    if (px == 0 || px == PW_ - 1 || py == 0 || py == PH_ - 1) { Xp[oidx] = 0ull; return; }
    const float* xp = x + (((size_t)n * C_ + j * 64) * H_ + (py - 1)) * W_ + (px - 1);
    u64 bits = 0ull;
    #pragma unroll 8
    for (int cl = 0; cl < 64; ++cl)
        bits |= (u64)(xp[(size_t)cl * PIX_] > 0.0f) << cl;
    Xp[oidx] = bits;
}

// ============================ hot kernel: XNOR-popcount conv ============================
// thread = (cout, half-of-256-cin); 4 output pixels per iteration (6 shared col loads);
// packed shfl merge of halves; fused BN statistics.
__device__ __forceinline__ int pop4(uint4 x, uint4 w) {
    return __popc(x.x ^ w.x) + __popc(x.y ^ w.y) + __popc(x.z ^ w.z) + __popc(x.w ^ w.w);
}

__global__ __launch_bounds__(256, 3)
void conv_pop_k(const u64* __restrict__ Xp,
                const u64* __restrict__ Wp,
                const int* __restrict__ corr,
                short* __restrict__ S,
                ull* __restrict__ sum, ull* __restrict__ sq)
{
    __shared__ u64 sx[3 * PW_ * NW_];     // 696 u64 = 5568 B
    const int t    = threadIdx.x;
    const int half = t & 1;
    const int c    = blockIdx.z * 128 + (t >> 1);
    const int oy   = blockIdx.x;
    const int n    = blockIdx.y;

    // this thread's half of the weights: 9 taps x 4 u32
    uint4 w[9];
    #pragma unroll
    for (int tp = 0; tp < 9; ++tp)
        w[tp] = *(const uint4*)&Wp[((size_t)tp * C_ + c) * NW_ + half * 2];

    const int rt = (oy == 0) ? 0 : ((oy == H_ - 1) ? 2 : 1);
    const int cL = corr[(rt * 3 + 0) * C_ + c];
    const int cM = corr[(rt * 3 + 1) * C_ + c];
    const int cR = corr[(rt * 3 + 2) * C_ + c];

    // load 3 padded rows (contiguous) into smem: 348 ulonglong2 by 256 threads
    {
        const ulonglong2* src = (const ulonglong2*)(Xp + (((size_t)n * PH_ + oy) * PW_) * NW_);
        ulonglong2* dst = (ulonglong2*)sx;
        for (int i = t; i < 3 * PW_ * NW_ / 2; i += 256) dst[i] = src[i];
    }
    __syncthreads();

    int ss = 0, qq = 0;
    const size_t rowbase = (((size_t)n * H_ + oy) * W_) * C_ + c;

    #pragma unroll 1
    for (int ox = 0; ox < W_; ox += 4) {
        int acc0 = 0, acc1 = 0, acc2 = 0, acc3 = 0;
        #pragma unroll
        for (int ky = 0; ky < 3; ++ky) {
            const u64* rowp = &sx[(ky * PW_ + ox) * NW_ + half * 2];
            #pragma unroll
            for (int col = 0; col < 6; ++col) {
                const uint4 xv = *(const uint4*)(rowp + (size_t)col * NW_);
                if (col <= 2)             acc0 += pop4(xv, w[ky * 3 + col]);
                if (col >= 1 && col <= 3) acc1 += pop4(xv, w[ky * 3 + col - 1]);
                if (col >= 2 && col <= 4) acc2 += pop4(xv, w[ky * 3 + col - 2]);
                if (col >= 3)             acc3 += pop4(xv, w[ky * 3 + col - 3]);
            }
        }
        // merge halves: pack two accs (<4096) per u32, one shfl each
        unsigned p01 = (unsigned)acc0 | ((unsigned)acc1 << 16);
        unsigned p23 = (unsigned)acc2 | ((unsigned)acc3 << 16);
        unsigned f01 = p01 + __shfl_xor_sync(0xffffffffu, p01, 1);
        unsigned f23 = p23 + __shfl_xor_sync(0xffffffffu, p23, 1);
        // even thread finishes pixels ox,ox+1; odd finishes ox+2,ox+3
        const unsigned fsel = half ? f23 : f01;
        const int gx = ox + half * 2;
        const int fa = (int)(fsel & 0xffffu);
        const int fb = (int)(fsel >> 16);
        const int sa = 2304 - 2 * fa - ((gx == 0) ? cL : cM);
        const int sb = 2304 - 2 * fb - ((gx + 1 == W_ - 1) ? cR : cM);
        const size_t pb = rowbase + (size_t)gx * C_;
        S[pb]      = (short)sa;
        S[pb + C_] = (short)sb;
        ss += sa + sb;
        qq += sa * sa + sb * sb;
    }
    atomicAdd(&sum[c], (ull)(long long)ss);
    atomicAdd(&sq[c],  (ull)(long long)qq);
}

// ============================ bn / thresh / final ============================
__global__ void bnparams_k(const ull* __restrict__ sum, const ull* __restrict__ sq,
                           const float* __restrict__ gamma, const float* __restrict__ beta,
                           float* __restrict__ a, float* __restrict__ b) {
    int c = threadIdx.x;
    const double M = (double)M_CNT_;
    double mS = (double)(long long)sum[c] / M;
    double vS = (double)(long long)sq[c] / M - mS * mS;
    double m = 0.5 * mS;            // y = 0.5 * S
    double v = 0.25 * vS;
    double r = 1.0 / sqrt(v + 1e-5);
    double g = (double)gamma[c];
    a[c] = (float)(0.5 * r * g);
    b[c] = (float)((double)beta[c] - m * r * g);
}

// threshold conv1 sums -> packed padded bitplanes via warp ballot
__global__ void thresh_ballot_k(const short* __restrict__ S,
                                const float* __restrict__ a, const float* __restrict__ b,
                                u64* __restrict__ Xp2) {
    int c = threadIdx.x;            // 0..255
    int py = blockIdx.x, n = blockIdx.y;
    int warp = c >> 5, lane = c & 31;
    float av = a[c], bv = b[c];
    bool rowv = (py >= 1 && py <= H_);
    for (int px = 0; px < PW_; ++px) {
        unsigned bit = 0u;
        if (rowv && px >= 1 && px <= W_) {
            int v = S[(((size_t)n * H_ + (py - 1)) * W_ + (px - 1)) * C_ + c];
            bit = (av * (float)v + bv > 0.0f) ? 1u : 0u;
        }
        unsigned m = __ballot_sync(0xffffffffu, bit);
        if (lane == 0)
            ((unsigned*)(Xp2 + (((size_t)n * PH_ + py) * PW_ + px) * NW_))[warp] = m;
    }
}

// final: out = clip(a2*S2 + b2 + x, -1, 1), smem transpose (3136 = 98*32)
__global__ __launch_bounds__(256)
void final_k(const short* __restrict__ S2,
             const float* __restrict__ a, const float* __restrict__ b,
             const float* __restrict__ x, float* __restrict__ out) {
    __shared__ short tile[32][33];
    int n = blockIdx.z, pt = blockIdx.x, ct = blockIdx.y;
    int tx = threadIdx.x, ty = threadIdx.y;      // (32, 8)
    #pragma unroll
    for (int i = 0; i < 4; ++i) {
        int rl = ty + i * 8;
        tile[rl][tx] = S2[((size_t)n * PIX_ + pt * 32 + rl) * C_ + ct * 32 + tx];
    }
    __syncthreads();
    int p = pt * 32 + tx;
    int py = p / W_, px = p % W_;
    #pragma unroll
    for (int i = 0; i < 4; ++i) {
        int cl = ty + i * 8;
        int cc = ct * 32 + cl;
        size_t oi = (((size_t)n * C_ + cc) * H_ + py) * W_ + px;
        float v = a[cc] * (float)tile[tx][cl] + b[cc] + x[oi];
        out[oi] = fminf(1.0f, fmaxf(-1.0f, v));
    }
}

// ============================ launch ============================
extern "C" void kernel_launch(void* const* d_in, const int* in_sizes, int n_in,
                              void* d_out, int out_size) {
    const float* x  = (const float*)d_in[0];
    const float* w1 = (const float*)d_in[1];
    const float* g1 = (const float*)d_in[2];
    const float* b1 = (const float*)d_in[3];
    const float* w2 = (const float*)d_in[4];
    const float* g2 = (const float*)d_in[5];
    const float* b2 = (const float*)d_in[6];
    float* out = (float*)d_out;

    void *pX1, *pX2, *pW1, *pW2, *pc1, *pc2, *pS1, *pS2;
    void *psum1, *psq1, *psum2, *psq2, *pa1, *pb1, *pa2, *pb2;
    cudaGetSymbolAddress(&pX1, g_Xp1);  cudaGetSymbolAddress(&pX2, g_Xp2);
    cudaGetSymbolAddress(&pW1, g_Wp1);  cudaGetSymbolAddress(&pW2, g_Wp2);
    cudaGetSymbolAddress(&pc1, g_c1);   cudaGetSymbolAddress(&pc2, g_c2);
    cudaGetSymbolAddress(&pS1, g_S1);   cudaGetSymbolAddress(&pS2, g_S2);
    cudaGetSymbolAddress(&psum1, g_sum1); cudaGetSymbolAddress(&psq1, g_sq1);
    cudaGetSymbolAddress(&psum2, g_sum2); cudaGetSymbolAddress(&psq2, g_sq2);
    cudaGetSymbolAddress(&pa1, g_a1);   cudaGetSymbolAddress(&pb1, g_b1);
    cudaGetSymbolAddress(&pa2, g_a2);   cudaGetSymbolAddress(&pb2, g_b2);

    // setup (cheap)
    pack_w_k<<<9, 256>>>(w1, (u64*)pW1);
    pack_w_k<<<9, 256>>>(w2, (u64*)pW2);
    corr_w_k<<<1, 256>>>((const u64*)pW1, (int*)pc1);
    corr_w_k<<<1, 256>>>((const u64*)pW2, (int*)pc2);
    zero_stats_k<<<1, 256>>>();
    pack_x_k<<<dim3(PH_, N_), dim3(PW_, NW_)>>>(x, (u64*)pX1);

    // conv1 (+fused stats)
    conv_pop_k<<<dim3(H_, N_, 2), 256>>>((const u64*)pX1, (const u64*)pW1,
                                         (const int*)pc1, (short*)pS1,
                                         (ull*)psum1, (ull*)psq1);
    bnparams_k<<<1, 256>>>((const ull*)psum1, (const ull*)psq1, g1, b1,
                           (float*)pa1, (float*)pb1);
    thresh_ballot_k<<<dim3(PH_, N_), 256>>>((const short*)pS1,
        (const float*)pa1, (const float*)pb1, (u64*)pX2);

    // conv2 (+fused stats)
    conv_pop_k<<<dim3(H_, N_, 2), 256>>>((const u64*)pX2, (const u64*)pW2,
                                         (const int*)pc2, (short*)pS2,
                                         (ull*)psum2, (ull*)psq2);
    bnparams_k<<<1, 256>>>((const ull*)psum2, (const ull*)psq2, g2, b2,
                           (float*)pa2, (float*)pb2);

    final_k<<<dim3(PIX_ / 32, 8, N_), dim3(32, 8)>>>(
        (const short*)pS2, (const float*)pa2, (const float*)pb2, x, out);
}